// round 8
// baseline (speedup 1.0000x reference)
#include <cuda_runtime.h>

// ---------------- problem constants ----------------------------------------
#define BGRAPH 1024
#define FN     32
#define DIN    64
#define HID    128
#define NHEADS 4
#define EPG    256
#define ETOT   (EPG + FN)       // 288
#define H4     (NHEADS * HID)   // 512
#define H1PAD  520
#define NTH    512

// ---------------- shared memory layout (float offsets) ---------------------
#define SM_H1   0                      // H1 [32][520] = 16640 (AL [32][128] overlays)
#define SM_X    16640                  // X [32][128] = 4096
#define SM_YH   20736                  // yT [128][34] = 4352 (embT [64][34] overlays)
#define SM_A1H  25088                  // A1h [32][34] = 1088
#define SM_LB   26176                  // 288
#define SM_AS1  26464                  // 128
#define SM_AD1  26592                  // 128
#define SM_AS2  26720                  // 32
#define SM_AD2  26752                  // 32
#define SM_DN2  26784                  // 32
#define SM_IV2  26816                  // 32
#define SM_CSR  26848                  // 32
#define SM_ZB   26880                  // 512
#define SM_PS   27392                  // 512
#define SM_NF   27904
#define SM_NI   (2 * ETOT)             // sSL, sDL = 576
#define SMEM_BYTES ((SM_NF + SM_NI) * 4)   // 113,920 B -> 2 CTAs/SM

typedef unsigned long long ull;

__device__ float g_wts1[512];   // [h][k] = sum_c W1[k, h*128+c] * att_src1[h,c]
__device__ float g_wtd1[512];
__device__ float g_wt2s[512];   // [k]    = sum_c W2[k,c] * att_src2[c]
__device__ float g_wt2d[512];

__device__ __forceinline__ ull pk2(float x, float y) {
    ull r; asm("mov.b64 %0, {%1,%2};" : "=l"(r) : "f"(x), "f"(y)); return r;
}
__device__ __forceinline__ ull splat2(float x) { return pk2(x, x); }
__device__ __forceinline__ void upk2(ull p, float& x, float& y) {
    asm("mov.b64 {%0,%1}, %2;" : "=f"(x), "=f"(y) : "l"(p));
}
__device__ __forceinline__ void fma2(ull& d, ull a, ull b) {
    asm("fma.rn.f32x2 %0, %1, %2, %0;" : "+l"(d) : "l"(a), "l"(b));
}
__device__ __forceinline__ void mul2(ull& d, ull b) {
    asm("mul.rn.f32x2 %0, %0, %1;" : "+l"(d) : "l"(b));
}
__device__ __forceinline__ float dot4(const float4& a, const float4& b) {
    return fmaf(a.x, b.x, fmaf(a.y, b.y, fmaf(a.z, b.z, a.w * b.w)));
}
__device__ __forceinline__ float wredsum(float v) {
    #pragma unroll
    for (int o = 16; o; o >>= 1) v += __shfl_xor_sync(0xffffffffu, v, o);
    return v;
}
__device__ __forceinline__ float elu1(float x) {
    return (x > 0.f) ? x : expm1f(x);
}

// ---------------- pre-kernel: project attention vectors through weights ----
__global__ void precomp_kernel(const float* __restrict__ W1,
                               const float* __restrict__ as1w,
                               const float* __restrict__ ad1w,
                               const float* __restrict__ W2,
                               const float* __restrict__ as2w,
                               const float* __restrict__ ad2w)
{
    int t = blockIdx.x * blockDim.x + threadIdx.x;   // 0..1023
    if (t < 512) {
        int h = t >> 7, k = t & 127;
        const float* wrow = W1 + k * H4 + h * HID;
        const float* aw = as1w + h * HID;
        const float* dw = ad1w + h * HID;
        float s = 0.f, d = 0.f;
        #pragma unroll 4
        for (int c = 0; c < HID; ++c) {
            s = fmaf(wrow[c], aw[c], s);
            d = fmaf(wrow[c], dw[c], d);
        }
        g_wts1[t] = s; g_wtd1[t] = d;
    } else {
        int k = t - 512;
        const float* wrow = W2 + k * HID;
        float s = 0.f, d = 0.f;
        #pragma unroll 4
        for (int c = 0; c < HID; ++c) {
            s = fmaf(wrow[c], as2w[c], s);
            d = fmaf(wrow[c], ad2w[c], d);
        }
        g_wt2s[k] = s; g_wt2d[k] = d;
    }
}

__global__ __launch_bounds__(NTH, 2)
void gat_fused_kernel(
    const float* __restrict__ emb,    const float* __restrict__ Wal,
    const float* __restrict__ bal,    const float* __restrict__ lng,
    const float* __restrict__ lnb,    const float* __restrict__ gatel,
    const float* __restrict__ W1,     const float* __restrict__ b1,
    const float* __restrict__ W2,     const float* __restrict__ b2,
    const int*   __restrict__ esrc,   const int*   __restrict__ edst,
    float*       __restrict__ out,    int write_gate)
{
    extern __shared__ float sm[];
    float* H1   = sm + SM_H1;             // [32][520]
    float* AL   = sm + SM_H1;             // [32][128] overlay (dead before H1)
    float* X    = sm + SM_X;              // [32][128]
    float* YH   = sm + SM_YH;             // [128][34] per-head y^T
    float* embT = sm + SM_YH;             // [64][34] overlay (dead before YH)
    float* A1H  = sm + SM_A1H;            // [32][34] per-head alpha-exp
    float* lbuf = sm + SM_LB;
    float* as1  = sm + SM_AS1;
    float* ad1  = sm + SM_AD1;
    float* as2  = sm + SM_AS2;
    float* ad2  = sm + SM_AD2;
    float* dn2  = sm + SM_DN2;
    float* iv2  = sm + SM_IV2;
    float* csr  = sm + SM_CSR;
    float* zb   = sm + SM_ZB;
    float* ps   = sm + SM_PS;
    int* sSL = (int*)(sm + SM_NF);
    int* sDL = sSL + ETOT;

    const int g    = blockIdx.x;
    const int tid  = threadIdx.x;
    const int lane = tid & 31;
    const int wid  = tid >> 5;

    // ---------- Phase 0: stage embT + edges, zero accumulators -------------
    {
        float4 v = ((const float4*)emb)[(size_t)g * (FN * DIN / 4) + tid];
        int r  = tid >> 4;
        int c4 = tid & 15;
        embT[(c4 * 4 + 0) * 34 + r] = v.x;
        embT[(c4 * 4 + 1) * 34 + r] = v.y;
        embT[(c4 * 4 + 2) * 34 + r] = v.z;
        embT[(c4 * 4 + 3) * 34 + r] = v.w;
    }
    if (tid >= 256) {
        int t = tid - 256;
        sSL[t] = esrc[g * EPG + t] - g * FN;
        sDL[t] = edst[g * EPG + t] - g * FN;
    }
    if (tid < 32) {
        sSL[EPG + tid] = tid;  sDL[EPG + tid] = tid;   // self loops
        as2[tid] = 0.f; ad2[tid] = 0.f; dn2[tid] = 0.f; csr[tid] = 0.f;
    }
    __syncthreads();

    // ---------- Phase 1: align GEMM (16 warps x 2 rows) -> AL --------------
    {
        ull acc[4];
        #pragma unroll
        for (int j = 0; j < 4; ++j) acc[j] = 0ULL;
        const float4* Wp = (const float4*)Wal + lane;
        #pragma unroll 4
        for (int k = 0; k < DIN; ++k) {
            float4 b = Wp[k * 32];
            ull a0 = *(const ull*)(embT + k * 34 + wid * 2);
            fma2(acc[0], a0, splat2(b.x));
            fma2(acc[1], a0, splat2(b.y));
            fma2(acc[2], a0, splat2(b.z));
            fma2(acc[3], a0, splat2(b.w));
        }
        float4 bb = ((const float4*)bal)[lane];
        float4 r0, r1;
        upk2(acc[0], r0.x, r1.x); upk2(acc[1], r0.y, r1.y);
        upk2(acc[2], r0.z, r1.z); upk2(acc[3], r0.w, r1.w);
        r0.x += bb.x; r0.y += bb.y; r0.z += bb.z; r0.w += bb.w;
        r1.x += bb.x; r1.y += bb.y; r1.z += bb.z; r1.w += bb.w;
        ((float4*)(AL + (wid * 2) * HID))[lane]     = r0;
        ((float4*)(AL + (wid * 2 + 1) * HID))[lane] = r1;
    }
    __syncthreads();

    // ---------- Phase 2: LayerNorm + gate -> X; fused logits1 --------------
    {
        #pragma unroll
        for (int rr = 0; rr < 2; ++rr) {
            int r = wid * 2 + rr;
            float v[4];
            float s = 0.f, s2 = 0.f;
            #pragma unroll
            for (int j = 0; j < 4; ++j) {
                v[j] = AL[r * HID + j * 32 + lane];
                s  += v[j];
                s2 += v[j] * v[j];
            }
            s  = wredsum(s);
            s2 = wredsum(s2);
            float mean = s * (1.f / HID);
            float var  = s2 * (1.f / HID) - mean * mean;
            float rstd = rsqrtf(var + 1e-5f);
            float gate = 1.f / (1.f + __expf(-gatel[r]));
            float ss[4] = {0.f, 0.f, 0.f, 0.f};
            float dd[4] = {0.f, 0.f, 0.f, 0.f};
            #pragma unroll
            for (int j = 0; j < 4; ++j) {
                int c = j * 32 + lane;
                float xc = ((v[j] - mean) * rstd * lng[c] + lnb[c]) * gate;
                X[r * HID + c] = xc;
                #pragma unroll
                for (int h = 0; h < 4; ++h) {
                    ss[h] = fmaf(xc, g_wts1[h * HID + c], ss[h]);
                    dd[h] = fmaf(xc, g_wtd1[h * HID + c], dd[h]);
                }
            }
            #pragma unroll
            for (int h = 0; h < 4; ++h) {
                float s1 = wredsum(ss[h]);
                float d1 = wredsum(dd[h]);
                if (lane == 0) { as1[r * 4 + h] = s1; ad1[r * 4 + h] = d1; }
            }
        }
    }

    // =============== head loop: conv1 one head at a time ===================
    #pragma unroll 1
    for (int h = 0; h < NHEADS; ++h) {
        __syncthreads();                       // AL/X ready; prev YH consumed
        // zero A1h
        for (int i = tid; i < FN * 34; i += NTH) A1H[i] = 0.f;
        __syncthreads();
        // edge pass -> dense per-head alpha-exp
        if (tid < ETOT) {
            int s = sSL[tid], d = sDL[tid];
            float l = as1[s * 4 + h] + ad1[d * 4 + h];
            l = (l > 0.f) ? l : 0.2f * l;
            atomicAdd(&A1H[s * 34 + d], __expf(l));
        }
        __syncthreads();

        // ---- P4h: y^T[k][d] = sum_s A1h[s,d] X[s,k], normalized ----------
        {
            const int dg = wid & 3;            // d-octet dg*8..+7
            const int qg = wid >> 2;           // k = qg*32 + lane
            const int k  = qg * 32 + lane;
            int myd = dg * 8 + (lane & 7);
            float sum = 0.f;
            #pragma unroll 8
            for (int s = 0; s < FN; ++s) sum += A1H[s * 34 + myd];
            float myinv = __fdividef(1.f, sum);
            ull acc[4];
            #pragma unroll
            for (int dp = 0; dp < 4; ++dp) acc[dp] = 0ULL;
            #pragma unroll 2
            for (int s = 0; s < FN; ++s) {
                const ull* ar = (const ull*)(A1H + s * 34 + dg * 8);
                ull a0 = ar[0], a1 = ar[1], a2 = ar[2], a3 = ar[3];
                ull x = splat2(X[s * HID + k]);
                fma2(acc[0], a0, x); fma2(acc[1], a1, x);
                fma2(acc[2], a2, x); fma2(acc[3], a3, x);
            }
            #pragma unroll
            for (int dp = 0; dp < 4; ++dp) {
                float i0 = __shfl_sync(0xffffffffu, myinv, 2 * dp);
                float i1 = __shfl_sync(0xffffffffu, myinv, 2 * dp + 1);
                ull iv = pk2(i0, i1);
                mul2(acc[dp], iv);
                *(ull*)(YH + k * 34 + dg * 8 + 2 * dp) = acc[dp];
            }
        }
        __syncthreads();

        // ---- P5h: H1[:, hblk] = ELU(y @ W1h + b1h); logits2 partials -----
        // acc[j] -> col h*128 + lane*4 + j (float4 component mapping)
        {
            const int rp = wid;                // row-pair rp*2, rp*2+1
            ull acc[4];
            #pragma unroll
            for (int j = 0; j < 4; ++j) acc[j] = 0ULL;
            const float4* Wp = (const float4*)W1 + h * 32 + lane;
            const float* yk = YH + rp * 2;
            #pragma unroll 4
            for (int k = 0; k < HID; ++k) {
                float4 w = Wp[k * 128];
                ull a = *(const ull*)(yk + k * 34);
                fma2(acc[0], a, splat2(w.x));
                fma2(acc[1], a, splat2(w.y));
                fma2(acc[2], a, splat2(w.z));
                fma2(acc[3], a, splat2(w.w));
            }
            float4 bb  = ((const float4*)b1)[h * 32 + lane];
            float4 w2s = ((const float4*)g_wt2s)[h * 32 + lane];
            float4 w2d = ((const float4*)g_wt2d)[h * 32 + lane];
            float4 r0, r1;
            upk2(acc[0], r0.x, r1.x); upk2(acc[1], r0.y, r1.y);
            upk2(acc[2], r0.z, r1.z); upk2(acc[3], r0.w, r1.w);
            r0.x = elu1(r0.x + bb.x); r0.y = elu1(r0.y + bb.y);
            r0.z = elu1(r0.z + bb.z); r0.w = elu1(r0.w + bb.w);
            r1.x = elu1(r1.x + bb.x); r1.y = elu1(r1.y + bb.y);
            r1.z = elu1(r1.z + bb.z); r1.w = elu1(r1.w + bb.w);
            int d0 = rp * 2;
            ((float4*)(H1 + d0 * H1PAD + h * HID))[lane]       = r0;
            ((float4*)(H1 + (d0 + 1) * H1PAD + h * HID))[lane] = r1;
            float s0  = wredsum(dot4(r0, w2s));
            float d0s = wredsum(dot4(r0, w2d));
            float s1  = wredsum(dot4(r1, w2s));
            float d1s = wredsum(dot4(r1, w2d));
            if (lane == 0) {
                atomicAdd(&as2[d0], s0);
                atomicAdd(&ad2[d0], d0s);
                atomicAdd(&as2[d0 + 1], s1);
                atomicAdd(&ad2[d0 + 1], d1s);
            }
        }
    }
    __syncthreads();

    // ---------- Phase 6: edge pass 2 (lbuf) -> csr -------------------------
    if (tid < ETOT) {
        int s = sSL[tid], d = sDL[tid];
        float l = as2[s] + ad2[d];
        l = (l > 0.f) ? l : 0.2f * l;
        float ex = __expf(l);
        lbuf[tid] = ex;
        atomicAdd(&dn2[d], ex);
    }
    __syncthreads();
    if (tid < 32) iv2[tid] = __fdividef(1.f, dn2[tid] * (float)FN);
    __syncthreads();
    if (tid < ETOT) {
        atomicAdd(&csr[sSL[tid]], lbuf[tid] * iv2[sDL[tid]]);
    }
    __syncthreads();

    // ---------- Phase 7: zbar[k] = sum_s csr[s] * H1[s,k] ------------------
    {
        float acc = 0.f;
        #pragma unroll 8
        for (int s = 0; s < FN; ++s) acc = fmaf(csr[s], H1[s * H1PAD + tid], acc);
        zb[tid] = acc;
    }
    __syncthreads();

    // ---------- Phase 8: out = zbar @ W2 + b2 (4-way k-split) --------------
    {
        const int cc = tid & 127;
        const int ks = tid >> 7;             // 4 k-splits of 128
        const float* w2 = W2 + (ks * 128) * HID + cc;
        const float* zp = zb + ks * 128;
        float a0 = 0.f, a1 = 0.f, a2 = 0.f, a3 = 0.f;
        #pragma unroll 8
        for (int k = 0; k < 128; k += 4) {
            a0 = fmaf(zp[k + 0], w2[(k + 0) * HID], a0);
            a1 = fmaf(zp[k + 1], w2[(k + 1) * HID], a1);
            a2 = fmaf(zp[k + 2], w2[(k + 2) * HID], a2);
            a3 = fmaf(zp[k + 3], w2[(k + 3) * HID], a3);
        }
        ps[tid] = (a0 + a1) + (a2 + a3);
    }
    __syncthreads();
    if (tid < HID) {
        float tot = ps[tid] + ps[128 + tid] + ps[256 + tid] + ps[384 + tid];
        out[(size_t)g * HID + tid] = tot + b2[tid];
    }
    if (write_gate && g == 0 && tid < FN) {
        out[(size_t)BGRAPH * HID + tid] = 1.f / (1.f + __expf(-gatel[tid]));
    }
}

extern "C" void kernel_launch(void* const* d_in, const int* in_sizes, int n_in,
                              void* d_out, int out_size)
{
    const float* emb   = (const float*)d_in[0];
    const float* Wal   = (const float*)d_in[1];
    const float* bal   = (const float*)d_in[2];
    const float* lng   = (const float*)d_in[3];
    const float* lnb   = (const float*)d_in[4];
    const float* gatel = (const float*)d_in[5];
    const float* W1    = (const float*)d_in[6];
    const float* as1w  = (const float*)d_in[7];
    const float* ad1w  = (const float*)d_in[8];
    const float* b1    = (const float*)d_in[9];
    const float* W2    = (const float*)d_in[10];
    const float* as2w  = (const float*)d_in[11];
    const float* ad2w  = (const float*)d_in[12];
    const float* b2    = (const float*)d_in[13];
    const int*   ei    = (const int*)d_in[14];

    const int Et = in_sizes[14] / 2;
    const int* esrc = ei;
    const int* edst = ei + Et;
    const int write_gate = (out_size >= BGRAPH * HID + FN) ? 1 : 0;

    cudaFuncSetAttribute(gat_fused_kernel,
                         cudaFuncAttributeMaxDynamicSharedMemorySize, SMEM_BYTES);

    precomp_kernel<<<2, 512>>>(W1, as1w, ad1w, W2, as2w, ad2w);
    gat_fused_kernel<<<BGRAPH, NTH, SMEM_BYTES>>>(
        emb, Wal, bal, lng, lnb, gatel,
        W1, b1, W2, b2,
        esrc, edst, (float*)d_out, write_gate);
}

// round 9
// speedup vs baseline: 1.2250x; 1.2250x over previous
#include <cuda_runtime.h>

// ---------------- problem constants ----------------------------------------
#define BGRAPH 1024
#define FN     32
#define DIN    64
#define HID    128
#define NHEADS 4
#define EPG    256
#define ETOT   (EPG + FN)       // 288
#define H4     (NHEADS * HID)   // 512
#define XPAD   132
#define H1PAD  516
#define YTPAD  34
#define A1PAD  34
#define NTH    1024

// ---------------- shared memory layout (float offsets) ---------------------
#define SM_YT   0                      // yT [4][128][34] = 17408 (embT overlays)
#define SM_X    17408                  // X [32][132] = 4224; H1 [32][516] overlay
#define SM_A1   33920                  // [4][32][34] = 4352
#define SM_LB   38272                  // 288
#define SM_AS1  38560                  // 128
#define SM_AD1  38688                  // 128
#define SM_AS2  38816                  // 32
#define SM_AD2  38848                  // 32
#define SM_DN2  38880                  // 32
#define SM_IV2  38912                  // 32
#define SM_CSR  38944                  // 32
#define SM_ZB   38976                  // 512
#define SM_PS   39488                  // 1024
#define SM_NF   40512
#define SM_NI   (2 * ETOT)             // 576 ints
#define SMEM_BYTES ((SM_NF + SM_NI) * 4)   // 164,352 B

typedef unsigned long long ull;

__device__ float g_wts1[512];   // [h][k] = sum_c W1[k, h*128+c] * att_src1[h,c]
__device__ float g_wtd1[512];
__device__ float g_wt2s[512];   // [k]    = sum_c W2[k,c] * att_src2[c]
__device__ float g_wt2d[512];

__device__ __forceinline__ ull pk2(float x, float y) {
    ull r; asm("mov.b64 %0, {%1,%2};" : "=l"(r) : "f"(x), "f"(y)); return r;
}
__device__ __forceinline__ ull splat2(float x) { return pk2(x, x); }
__device__ __forceinline__ void upk2(ull p, float& x, float& y) {
    asm("mov.b64 {%0,%1}, %2;" : "=f"(x), "=f"(y) : "l"(p));
}
__device__ __forceinline__ void fma2(ull& d, ull a, ull b) {
    asm("fma.rn.f32x2 %0, %1, %2, %0;" : "+l"(d) : "l"(a), "l"(b));
}
__device__ __forceinline__ void mul2(ull& d, ull b) {
    asm("mul.rn.f32x2 %0, %0, %1;" : "+l"(d) : "l"(b));
}
__device__ __forceinline__ float dot4(const float4& a, const float4& b) {
    return fmaf(a.x, b.x, fmaf(a.y, b.y, fmaf(a.z, b.z, a.w * b.w)));
}
__device__ __forceinline__ float wredsum(float v) {
    #pragma unroll
    for (int o = 16; o; o >>= 1) v += __shfl_xor_sync(0xffffffffu, v, o);
    return v;
}
__device__ __forceinline__ float elu1(float x) {
    return (x > 0.f) ? x : expm1f(x);
}

// ---------------- pre-kernel: project attention vectors through weights ----
__global__ void precomp_kernel(const float* __restrict__ W1,
                               const float* __restrict__ as1w,
                               const float* __restrict__ ad1w,
                               const float* __restrict__ W2,
                               const float* __restrict__ as2w,
                               const float* __restrict__ ad2w)
{
    int t = blockIdx.x * blockDim.x + threadIdx.x;   // 0..1023
    if (t < 512) {
        int h = t >> 7, k = t & 127;
        const float* wrow = W1 + k * H4 + h * HID;
        const float* aw = as1w + h * HID;
        const float* dw = ad1w + h * HID;
        float s = 0.f, d = 0.f;
        #pragma unroll 4
        for (int c = 0; c < HID; ++c) {
            s = fmaf(wrow[c], aw[c], s);
            d = fmaf(wrow[c], dw[c], d);
        }
        g_wts1[t] = s; g_wtd1[t] = d;
    } else {
        int k = t - 512;
        const float* wrow = W2 + k * HID;
        float s = 0.f, d = 0.f;
        #pragma unroll 4
        for (int c = 0; c < HID; ++c) {
            s = fmaf(wrow[c], as2w[c], s);
            d = fmaf(wrow[c], ad2w[c], d);
        }
        g_wt2s[k] = s; g_wt2d[k] = d;
    }
}

__global__ __launch_bounds__(NTH, 1)
void gat_fused_kernel(
    const float* __restrict__ emb,    const float* __restrict__ Wal,
    const float* __restrict__ bal,    const float* __restrict__ lng,
    const float* __restrict__ lnb,    const float* __restrict__ gatel,
    const float* __restrict__ W1,     const float* __restrict__ b1,
    const float* __restrict__ W2,     const float* __restrict__ b2,
    const int*   __restrict__ esrc,   const int*   __restrict__ edst,
    float*       __restrict__ out,    int write_gate)
{
    extern __shared__ float sm[];
    float* yT   = sm + SM_YT;             // [4][128][34]
    float* embT = sm + SM_YT;             // [64][34] overlay (dead before yT)
    float* X    = sm + SM_X;              // [32][132]
    float* H1   = sm + SM_X;              // [32][516] overlay (X dead after P4)
    float* A1   = sm + SM_A1;
    float* lbuf = sm + SM_LB;
    float* as1  = sm + SM_AS1;
    float* ad1  = sm + SM_AD1;
    float* as2  = sm + SM_AS2;
    float* ad2  = sm + SM_AD2;
    float* dn2  = sm + SM_DN2;
    float* iv2  = sm + SM_IV2;
    float* csr  = sm + SM_CSR;
    float* zb   = sm + SM_ZB;
    float* ps   = sm + SM_PS;
    int* sSL = (int*)(sm + SM_NF);
    int* sDL = sSL + ETOT;

    const int g    = blockIdx.x;
    const int tid  = threadIdx.x;
    const int lane = tid & 31;
    const int wid  = tid >> 5;

    // ---------- Phase 0: stage embT + edges, zero accumulators -------------
    if (tid < 512) {
        float4 v = ((const float4*)emb)[(size_t)g * (FN * DIN / 4) + tid];
        int r  = tid >> 4;
        int c4 = tid & 15;
        embT[(c4 * 4 + 0) * YTPAD + r] = v.x;
        embT[(c4 * 4 + 1) * YTPAD + r] = v.y;
        embT[(c4 * 4 + 2) * YTPAD + r] = v.z;
        embT[(c4 * 4 + 3) * YTPAD + r] = v.w;
    } else if (tid < 768) {
        int t = tid - 512;
        sSL[t] = esrc[g * EPG + t] - g * FN;
        sDL[t] = edst[g * EPG + t] - g * FN;
    } else if (tid < 800) {
        int t = tid - 768;
        sSL[EPG + t] = t;
        sDL[EPG + t] = t;
    }
    for (int i = tid; i < (4 * FN * A1PAD) / 4; i += NTH)
        ((float4*)A1)[i] = make_float4(0.f, 0.f, 0.f, 0.f);
    if (tid < 32) { as2[tid] = 0.f; ad2[tid] = 0.f; dn2[tid] = 0.f; csr[tid] = 0.f; }
    __syncthreads();

    // ---------- Phase 1: align GEMM + in-register LN/gate/logits1 ----------
    if (wid < 16) {
        ull acc[4];
        #pragma unroll
        for (int j = 0; j < 4; ++j) acc[j] = 0ULL;
        const float4* Wp = (const float4*)Wal + lane;
        #pragma unroll 4
        for (int k = 0; k < DIN; ++k) {
            float4 b = Wp[k * 32];
            ull a0 = *(const ull*)(embT + k * YTPAD + wid * 2);
            fma2(acc[0], a0, splat2(b.x));
            fma2(acc[1], a0, splat2(b.y));
            fma2(acc[2], a0, splat2(b.z));
            fma2(acc[3], a0, splat2(b.w));
        }
        float4 bb = ((const float4*)bal)[lane];
        float4 r0, r1;
        upk2(acc[0], r0.x, r1.x); upk2(acc[1], r0.y, r1.y);
        upk2(acc[2], r0.z, r1.z); upk2(acc[3], r0.w, r1.w);
        r0.x += bb.x; r0.y += bb.y; r0.z += bb.z; r0.w += bb.w;
        r1.x += bb.x; r1.y += bb.y; r1.z += bb.z; r1.w += bb.w;
        float4 lg = ((const float4*)lng)[lane];
        float4 lb = ((const float4*)lnb)[lane];
        const int row0 = wid * 2;
        // LN stats (warp = full row)
        float s0 = wredsum(r0.x + r0.y + r0.z + r0.w);
        float q0 = wredsum(dot4(r0, r0));
        float s1 = wredsum(r1.x + r1.y + r1.z + r1.w);
        float q1 = wredsum(dot4(r1, r1));
        float m0 = s0 * (1.f / HID);
        float m1 = s1 * (1.f / HID);
        float rs0 = rsqrtf(q0 * (1.f / HID) - m0 * m0 + 1e-5f);
        float rs1 = rsqrtf(q1 * (1.f / HID) - m1 * m1 + 1e-5f);
        float g0 = 1.f / (1.f + __expf(-gatel[row0]));
        float g1 = 1.f / (1.f + __expf(-gatel[row0 + 1]));
        float4 x0, x1;
        x0.x = ((r0.x - m0) * rs0 * lg.x + lb.x) * g0;
        x0.y = ((r0.y - m0) * rs0 * lg.y + lb.y) * g0;
        x0.z = ((r0.z - m0) * rs0 * lg.z + lb.z) * g0;
        x0.w = ((r0.w - m0) * rs0 * lg.w + lb.w) * g0;
        x1.x = ((r1.x - m1) * rs1 * lg.x + lb.x) * g1;
        x1.y = ((r1.y - m1) * rs1 * lg.y + lb.y) * g1;
        x1.z = ((r1.z - m1) * rs1 * lg.z + lb.z) * g1;
        x1.w = ((r1.w - m1) * rs1 * lg.w + lb.w) * g1;
        ((float4*)(X + row0 * XPAD))[lane]       = x0;
        ((float4*)(X + (row0 + 1) * XPAD))[lane] = x1;
        #pragma unroll
        for (int h = 0; h < NHEADS; ++h) {
            float4 ws = ((const float4*)g_wts1)[h * 32 + lane];
            float4 wd = ((const float4*)g_wtd1)[h * 32 + lane];
            float a0s = wredsum(dot4(x0, ws));
            float a0d = wredsum(dot4(x0, wd));
            float a1s = wredsum(dot4(x1, ws));
            float a1d = wredsum(dot4(x1, wd));
            if (lane == 0) {
                as1[row0 * 4 + h] = a0s;       ad1[row0 * 4 + h] = a0d;
                as1[(row0 + 1) * 4 + h] = a1s; ad1[(row0 + 1) * 4 + h] = a1d;
            }
        }
    }
    __syncthreads();

    // ---------- Phase 3: edge pass 1 -> dense A1 (all threads) -------------
    {
        int e = tid >> 2, h = tid & 3;
        int s = sSL[e], d = sDL[e];
        float l = as1[s * 4 + h] + ad1[d * 4 + h];
        l = (l > 0.f) ? l : 0.2f * l;
        atomicAdd(&A1[(h * FN + s) * A1PAD + d], __expf(l));
        if (tid < 128) {
            int e2 = EPG + (tid >> 2);
            int s2 = sSL[e2];
            float l2 = as1[s2 * 4 + h] + ad1[s2 * 4 + h];
            l2 = (l2 > 0.f) ? l2 : 0.2f * l2;
            atomicAdd(&A1[(h * FN + s2) * A1PAD + s2], __expf(l2));
        }
    }
    __syncthreads();

    // ---------- Phase 4: y = A1n^T @ x (16 warps, inline inv1) -> yT -------
    if (wid < 16) {
        const int h  = wid >> 2;
        const int dg = wid & 3;
        // per-lane column sum -> inverse (lanes 0..7 hold d = dg*8..+7)
        int myd = dg * 8 + (lane & 7);
        float csum = 0.f;
        #pragma unroll 8
        for (int s = 0; s < FN; ++s) csum += A1[(h * FN + s) * A1PAD + myd];
        float myinv = __fdividef(1.f, csum);
        ull acc[4][4];                       // [q][dp]
        #pragma unroll
        for (int q = 0; q < 4; ++q)
            #pragma unroll
            for (int dp = 0; dp < 4; ++dp) acc[q][dp] = 0ULL;
        #pragma unroll 2
        for (int s = 0; s < FN; ++s) {
            const ull* ar = (const ull*)(A1 + (h * FN + s) * A1PAD + dg * 8);
            ull a0 = ar[0], a1 = ar[1], a2 = ar[2], a3 = ar[3];
            const float* xr = X + s * XPAD + lane;
            ull x0 = splat2(xr[0]);
            ull x1 = splat2(xr[32]);
            ull x2 = splat2(xr[64]);
            ull x3 = splat2(xr[96]);
            fma2(acc[0][0], a0, x0); fma2(acc[0][1], a1, x0);
            fma2(acc[0][2], a2, x0); fma2(acc[0][3], a3, x0);
            fma2(acc[1][0], a0, x1); fma2(acc[1][1], a1, x1);
            fma2(acc[1][2], a2, x1); fma2(acc[1][3], a3, x1);
            fma2(acc[2][0], a0, x2); fma2(acc[2][1], a1, x2);
            fma2(acc[2][2], a2, x2); fma2(acc[2][3], a3, x2);
            fma2(acc[3][0], a0, x3); fma2(acc[3][1], a1, x3);
            fma2(acc[3][2], a2, x3); fma2(acc[3][3], a3, x3);
        }
        ull iv[4];
        #pragma unroll
        for (int dp = 0; dp < 4; ++dp) {
            float i0 = __shfl_sync(0xffffffffu, myinv, 2 * dp);
            float i1 = __shfl_sync(0xffffffffu, myinv, 2 * dp + 1);
            iv[dp] = pk2(i0, i1);
        }
        #pragma unroll
        for (int q = 0; q < 4; ++q) {
            int k = lane + 32 * q;
            float* yb = yT + (h * HID + k) * YTPAD + dg * 8;
            #pragma unroll
            for (int dp = 0; dp < 4; ++dp) {
                mul2(acc[q][dp], iv[dp]);
                *(ull*)(yb + 2 * dp) = acc[q][dp];
            }
        }
    }
    __syncthreads();

    // ---------- Phase 5: h1 = ELU(y @ W1 + b1) (32 warps, 4 rows) ----------
    // acc[p][j] maps to column h*128 + lane*4 + j (float4 component mapping)
    {
        const int rg = wid >> 2;            // rows rg*4..+3 (2 pairs)
        const int h  = wid & 3;
        ull acc[2][4];
        #pragma unroll
        for (int p = 0; p < 2; ++p)
            #pragma unroll
            for (int j = 0; j < 4; ++j) acc[p][j] = 0ULL;
        const float4* Wp = (const float4*)W1 + h * 32 + lane;
        const float* yh = yT + h * HID * YTPAD + rg * 4;
        #pragma unroll 1
        for (int k0 = 0; k0 < HID; k0 += 4) {
            float4 bq[4];
            #pragma unroll
            for (int j = 0; j < 4; ++j) bq[j] = Wp[(k0 + j) * 128];
            #pragma unroll
            for (int j = 0; j < 4; ++j) {
                ull b0 = splat2(bq[j].x), b1v = splat2(bq[j].y);
                ull b2v = splat2(bq[j].z), b3 = splat2(bq[j].w);
                const ull* ap = (const ull*)(yh + (k0 + j) * YTPAD);
                ull a0 = ap[0], a1 = ap[1];
                fma2(acc[0][0], a0, b0); fma2(acc[0][1], a0, b1v);
                fma2(acc[0][2], a0, b2v); fma2(acc[0][3], a0, b3);
                fma2(acc[1][0], a1, b0); fma2(acc[1][1], a1, b1v);
                fma2(acc[1][2], a1, b2v); fma2(acc[1][3], a1, b3);
            }
        }
        float4 bb  = ((const float4*)b1)[h * 32 + lane];
        float4 w2s = ((const float4*)g_wt2s)[h * 32 + lane];
        float4 w2d = ((const float4*)g_wt2d)[h * 32 + lane];
        #pragma unroll
        for (int p = 0; p < 2; ++p) {
            int d0 = rg * 4 + p * 2;
            float4 r0, r1;
            upk2(acc[p][0], r0.x, r1.x); upk2(acc[p][1], r0.y, r1.y);
            upk2(acc[p][2], r0.z, r1.z); upk2(acc[p][3], r0.w, r1.w);
            r0.x = elu1(r0.x + bb.x); r0.y = elu1(r0.y + bb.y);
            r0.z = elu1(r0.z + bb.z); r0.w = elu1(r0.w + bb.w);
            r1.x = elu1(r1.x + bb.x); r1.y = elu1(r1.y + bb.y);
            r1.z = elu1(r1.z + bb.z); r1.w = elu1(r1.w + bb.w);
            ((float4*)(H1 + d0 * H1PAD + h * HID))[lane]       = r0;
            ((float4*)(H1 + (d0 + 1) * H1PAD + h * HID))[lane] = r1;
            float s0  = wredsum(dot4(r0, w2s));
            float d0s = wredsum(dot4(r0, w2d));
            float s1  = wredsum(dot4(r1, w2s));
            float d1s = wredsum(dot4(r1, w2d));
            if (lane == 0) {
                atomicAdd(&as2[d0], s0);
                atomicAdd(&ad2[d0], d0s);
                atomicAdd(&as2[d0 + 1], s1);
                atomicAdd(&ad2[d0 + 1], d1s);
            }
        }
    }
    __syncthreads();

    // ---------- Phase 6: edge pass 2 (lbuf) -> csr -------------------------
    if (tid < ETOT) {
        int s = sSL[tid], d = sDL[tid];
        float l = as2[s] + ad2[d];
        l = (l > 0.f) ? l : 0.2f * l;
        float ex = __expf(l);
        lbuf[tid] = ex;
        atomicAdd(&dn2[d], ex);
    }
    __syncthreads();
    if (tid < 32) iv2[tid] = __fdividef(1.f, dn2[tid] * (float)FN);
    __syncthreads();
    if (tid < ETOT) {
        atomicAdd(&csr[sSL[tid]], lbuf[tid] * iv2[sDL[tid]]);
    }
    __syncthreads();

    // ---------- Phase 7: zbar[k] = sum_s csr[s] * H1[s,k] ------------------
    if (tid < 512) {
        float acc = 0.f;
        #pragma unroll 8
        for (int s = 0; s < FN; ++s) acc = fmaf(csr[s], H1[s * H1PAD + tid], acc);
        zb[tid] = acc;
    }
    __syncthreads();

    // ---------- Phase 8: out = zbar @ W2 + b2 (8-way k-split) --------------
    {
        const int cc = tid & 127;
        const int ks = tid >> 7;             // 8 k-splits of 64
        const float* w2 = W2 + (ks * 64) * HID + cc;
        const float* zp = zb + ks * 64;
        float a0 = 0.f, a1 = 0.f, a2 = 0.f, a3 = 0.f;
        #pragma unroll 4
        for (int k = 0; k < 64; k += 4) {
            a0 = fmaf(zp[k + 0], w2[(k + 0) * HID], a0);
            a1 = fmaf(zp[k + 1], w2[(k + 1) * HID], a1);
            a2 = fmaf(zp[k + 2], w2[(k + 2) * HID], a2);
            a3 = fmaf(zp[k + 3], w2[(k + 3) * HID], a3);
        }
        ps[tid] = (a0 + a1) + (a2 + a3);
    }
    __syncthreads();
    if (tid < HID) {
        float tot = 0.f;
        #pragma unroll
        for (int q = 0; q < 8; ++q) tot += ps[q * 128 + tid];
        out[(size_t)g * HID + tid] = tot + b2[tid];
    }
    if (write_gate && g == 0 && tid < FN) {
        out[(size_t)BGRAPH * HID + tid] = 1.f / (1.f + __expf(-gatel[tid]));
    }
}

extern "C" void kernel_launch(void* const* d_in, const int* in_sizes, int n_in,
                              void* d_out, int out_size)
{
    const float* emb   = (const float*)d_in[0];
    const float* Wal   = (const float*)d_in[1];
    const float* bal   = (const float*)d_in[2];
    const float* lng   = (const float*)d_in[3];
    const float* lnb   = (const float*)d_in[4];
    const float* gatel = (const float*)d_in[5];
    const float* W1    = (const float*)d_in[6];
    const float* as1w  = (const float*)d_in[7];
    const float* ad1w  = (const float*)d_in[8];
    const float* b1    = (const float*)d_in[9];
    const float* W2    = (const float*)d_in[10];
    const float* as2w  = (const float*)d_in[11];
    const float* ad2w  = (const float*)d_in[12];
    const float* b2    = (const float*)d_in[13];
    const int*   ei    = (const int*)d_in[14];

    const int Et = in_sizes[14] / 2;
    const int* esrc = ei;
    const int* edst = ei + Et;
    const int write_gate = (out_size >= BGRAPH * HID + FN) ? 1 : 0;

    cudaFuncSetAttribute(gat_fused_kernel,
                         cudaFuncAttributeMaxDynamicSharedMemorySize, SMEM_BYTES);

    precomp_kernel<<<2, 512>>>(W1, as1w, ad1w, W2, as2w, ad2w);
    gat_fused_kernel<<<BGRAPH, NTH, SMEM_BYTES>>>(
        emb, Wal, bal, lng, lnb, gatel,
        W1, b1, W2, b2,
        esrc, edst, (float*)d_out, write_gate);
}

// round 10
// speedup vs baseline: 1.2380x; 1.0107x over previous
#include <cuda_runtime.h>

// ---------------- problem constants ----------------------------------------
#define BGRAPH 1024
#define FN     32
#define DIN    64
#define HID    128
#define NHEADS 4
#define EPG    256
#define ETOT   (EPG + FN)       // 288
#define H4     (NHEADS * HID)   // 512
#define XPAD   132
#define H1PAD  516
#define YTPAD  36              // yT stride (mult of 4 -> 16B-aligned row pairs)
#define ETPAD  34              // embT stride
#define A1PAD  34
#define NTH    1024

// ---------------- shared memory layout (float offsets) ---------------------
#define SM_YT   0                      // yT [4][128][36] = 18432 (embT overlays)
#define SM_X    18432                  // X [32][132] = 4224; H1 [32][516] overlay
#define SM_A1   34944                  // [4][32][34] = 4352
#define SM_LB   39296                  // 288
#define SM_AS1  39584                  // 128
#define SM_AD1  39712                  // 128
#define SM_AS2  39840                  // 32
#define SM_AD2  39872                  // 32
#define SM_DN2  39904                  // 32
#define SM_IV2  39936                  // 32
#define SM_CSR  39968                  // 32
#define SM_ZB   40000                  // 512
#define SM_PS   40512                  // 1024
#define SM_NF   41536
#define SM_NI   (2 * ETOT)             // 576 ints
#define SMEM_BYTES ((SM_NF + SM_NI) * 4)   // 168,448 B

typedef unsigned long long ull;

__device__ float g_wts1[512];   // [h][k] = sum_c W1[k, h*128+c] * att_src1[h,c]
__device__ float g_wtd1[512];
__device__ float g_wt2s[512];   // [k]    = sum_c W2[k,c] * att_src2[c]
__device__ float g_wt2d[512];

__device__ __forceinline__ ull pk2(float x, float y) {
    ull r; asm("mov.b64 %0, {%1,%2};" : "=l"(r) : "f"(x), "f"(y)); return r;
}
__device__ __forceinline__ ull splat2(float x) { return pk2(x, x); }
__device__ __forceinline__ void upk2(ull p, float& x, float& y) {
    asm("mov.b64 {%0,%1}, %2;" : "=f"(x), "=f"(y) : "l"(p));
}
__device__ __forceinline__ void fma2(ull& d, ull a, ull b) {
    asm("fma.rn.f32x2 %0, %1, %2, %0;" : "+l"(d) : "l"(a), "l"(b));
}
__device__ __forceinline__ void mul2(ull& d, ull b) {
    asm("mul.rn.f32x2 %0, %0, %1;" : "+l"(d) : "l"(b));
}
__device__ __forceinline__ float dot4(const float4& a, const float4& b) {
    return fmaf(a.x, b.x, fmaf(a.y, b.y, fmaf(a.z, b.z, a.w * b.w)));
}
__device__ __forceinline__ float wredsum(float v) {
    #pragma unroll
    for (int o = 16; o; o >>= 1) v += __shfl_xor_sync(0xffffffffu, v, o);
    return v;
}
__device__ __forceinline__ float elu1(float x) {
    return (x > 0.f) ? x : expm1f(x);
}

// ---------------- pre-kernel: project attention vectors through weights ----
__global__ void precomp_kernel(const float* __restrict__ W1,
                               const float* __restrict__ as1w,
                               const float* __restrict__ ad1w,
                               const float* __restrict__ W2,
                               const float* __restrict__ as2w,
                               const float* __restrict__ ad2w)
{
    int t = blockIdx.x * blockDim.x + threadIdx.x;   // 0..1023
    if (t < 512) {
        int h = t >> 7, k = t & 127;
        const float* wrow = W1 + k * H4 + h * HID;
        const float* aw = as1w + h * HID;
        const float* dw = ad1w + h * HID;
        float s = 0.f, d = 0.f;
        #pragma unroll 4
        for (int c = 0; c < HID; ++c) {
            s = fmaf(wrow[c], aw[c], s);
            d = fmaf(wrow[c], dw[c], d);
        }
        g_wts1[t] = s; g_wtd1[t] = d;
    } else {
        int k = t - 512;
        const float* wrow = W2 + k * HID;
        float s = 0.f, d = 0.f;
        #pragma unroll 4
        for (int c = 0; c < HID; ++c) {
            s = fmaf(wrow[c], as2w[c], s);
            d = fmaf(wrow[c], ad2w[c], d);
        }
        g_wt2s[k] = s; g_wt2d[k] = d;
    }
}

__global__ __launch_bounds__(NTH, 1)
void gat_fused_kernel(
    const float* __restrict__ emb,    const float* __restrict__ Wal,
    const float* __restrict__ bal,    const float* __restrict__ lng,
    const float* __restrict__ lnb,    const float* __restrict__ gatel,
    const float* __restrict__ W1,     const float* __restrict__ b1,
    const float* __restrict__ W2,     const float* __restrict__ b2,
    const int*   __restrict__ esrc,   const int*   __restrict__ edst,
    float*       __restrict__ out,    int write_gate)
{
    extern __shared__ float sm[];
    float* yT   = sm + SM_YT;             // [4][128][36]
    float* embT = sm + SM_YT;             // [64][34] overlay (dead before yT)
    float* X    = sm + SM_X;              // [32][132]
    float* H1   = sm + SM_X;              // [32][516] overlay (X dead after P4)
    float* A1   = sm + SM_A1;
    float* lbuf = sm + SM_LB;
    float* as1  = sm + SM_AS1;
    float* ad1  = sm + SM_AD1;
    float* as2  = sm + SM_AS2;
    float* ad2  = sm + SM_AD2;
    float* dn2  = sm + SM_DN2;
    float* iv2  = sm + SM_IV2;
    float* csr  = sm + SM_CSR;
    float* zb   = sm + SM_ZB;
    float* ps   = sm + SM_PS;
    int* sSL = (int*)(sm + SM_NF);
    int* sDL = sSL + ETOT;

    const int g    = blockIdx.x;
    const int tid  = threadIdx.x;
    const int lane = tid & 31;
    const int wid  = tid >> 5;

    // ---------- Phase 0: stage embT + edges, zero accumulators -------------
    if (tid < 512) {
        float4 v = ((const float4*)emb)[(size_t)g * (FN * DIN / 4) + tid];
        int r  = tid >> 4;
        int c4 = tid & 15;
        embT[(c4 * 4 + 0) * ETPAD + r] = v.x;
        embT[(c4 * 4 + 1) * ETPAD + r] = v.y;
        embT[(c4 * 4 + 2) * ETPAD + r] = v.z;
        embT[(c4 * 4 + 3) * ETPAD + r] = v.w;
    } else if (tid < 768) {
        int t = tid - 512;
        sSL[t] = esrc[g * EPG + t] - g * FN;
        sDL[t] = edst[g * EPG + t] - g * FN;
    } else if (tid < 800) {
        int t = tid - 768;
        sSL[EPG + t] = t;
        sDL[EPG + t] = t;
    }
    for (int i = tid; i < (4 * FN * A1PAD) / 4; i += NTH)
        ((float4*)A1)[i] = make_float4(0.f, 0.f, 0.f, 0.f);
    if (tid < 32) { as2[tid] = 0.f; ad2[tid] = 0.f; dn2[tid] = 0.f; csr[tid] = 0.f; }
    __syncthreads();

    // ---------- Phase 1: align GEMM + in-register LN/gate/logits1 ----------
    if (wid < 16) {
        ull acc[4];
        #pragma unroll
        for (int j = 0; j < 4; ++j) acc[j] = 0ULL;
        const float4* Wp = (const float4*)Wal + lane;
        #pragma unroll 4
        for (int k = 0; k < DIN; ++k) {
            float4 b = Wp[k * 32];
            ull a0 = *(const ull*)(embT + k * ETPAD + wid * 2);
            fma2(acc[0], a0, splat2(b.x));
            fma2(acc[1], a0, splat2(b.y));
            fma2(acc[2], a0, splat2(b.z));
            fma2(acc[3], a0, splat2(b.w));
        }
        float4 bb = ((const float4*)bal)[lane];
        float4 r0, r1;
        upk2(acc[0], r0.x, r1.x); upk2(acc[1], r0.y, r1.y);
        upk2(acc[2], r0.z, r1.z); upk2(acc[3], r0.w, r1.w);
        r0.x += bb.x; r0.y += bb.y; r0.z += bb.z; r0.w += bb.w;
        r1.x += bb.x; r1.y += bb.y; r1.z += bb.z; r1.w += bb.w;
        float4 lg = ((const float4*)lng)[lane];
        float4 lb = ((const float4*)lnb)[lane];
        const int row0 = wid * 2;
        float s0 = wredsum(r0.x + r0.y + r0.z + r0.w);
        float q0 = wredsum(dot4(r0, r0));
        float s1 = wredsum(r1.x + r1.y + r1.z + r1.w);
        float q1 = wredsum(dot4(r1, r1));
        float m0 = s0 * (1.f / HID);
        float m1 = s1 * (1.f / HID);
        float rs0 = rsqrtf(q0 * (1.f / HID) - m0 * m0 + 1e-5f);
        float rs1 = rsqrtf(q1 * (1.f / HID) - m1 * m1 + 1e-5f);
        float g0 = 1.f / (1.f + __expf(-gatel[row0]));
        float g1 = 1.f / (1.f + __expf(-gatel[row0 + 1]));
        float4 x0, x1;
        x0.x = ((r0.x - m0) * rs0 * lg.x + lb.x) * g0;
        x0.y = ((r0.y - m0) * rs0 * lg.y + lb.y) * g0;
        x0.z = ((r0.z - m0) * rs0 * lg.z + lb.z) * g0;
        x0.w = ((r0.w - m0) * rs0 * lg.w + lb.w) * g0;
        x1.x = ((r1.x - m1) * rs1 * lg.x + lb.x) * g1;
        x1.y = ((r1.y - m1) * rs1 * lg.y + lb.y) * g1;
        x1.z = ((r1.z - m1) * rs1 * lg.z + lb.z) * g1;
        x1.w = ((r1.w - m1) * rs1 * lg.w + lb.w) * g1;
        ((float4*)(X + row0 * XPAD))[lane]       = x0;
        ((float4*)(X + (row0 + 1) * XPAD))[lane] = x1;
        #pragma unroll
        for (int h = 0; h < NHEADS; ++h) {
            float4 ws = ((const float4*)g_wts1)[h * 32 + lane];
            float4 wd = ((const float4*)g_wtd1)[h * 32 + lane];
            float a0s = wredsum(dot4(x0, ws));
            float a0d = wredsum(dot4(x0, wd));
            float a1s = wredsum(dot4(x1, ws));
            float a1d = wredsum(dot4(x1, wd));
            if (lane == 0) {
                as1[row0 * 4 + h] = a0s;       ad1[row0 * 4 + h] = a0d;
                as1[(row0 + 1) * 4 + h] = a1s; ad1[(row0 + 1) * 4 + h] = a1d;
            }
        }
    }
    __syncthreads();

    // ---------- Phase 3: edge pass 1 -> dense A1 (all threads) -------------
    {
        int e = tid >> 2, h = tid & 3;
        int s = sSL[e], d = sDL[e];
        float l = as1[s * 4 + h] + ad1[d * 4 + h];
        l = (l > 0.f) ? l : 0.2f * l;
        atomicAdd(&A1[(h * FN + s) * A1PAD + d], __expf(l));
        if (tid < 128) {
            int e2 = EPG + (tid >> 2);
            int s2 = sSL[e2];
            float l2 = as1[s2 * 4 + h] + ad1[s2 * 4 + h];
            l2 = (l2 > 0.f) ? l2 : 0.2f * l2;
            atomicAdd(&A1[(h * FN + s2) * A1PAD + s2], __expf(l2));
        }
    }
    __syncthreads();

    // ---------- Phase 4: y = A1n^T @ x (16 warps, inline inv1) -> yT -------
    if (wid < 16) {
        const int h  = wid >> 2;
        const int dg = wid & 3;
        int myd = dg * 8 + (lane & 7);
        float csum = 0.f;
        #pragma unroll 8
        for (int s = 0; s < FN; ++s) csum += A1[(h * FN + s) * A1PAD + myd];
        float myinv = __fdividef(1.f, csum);
        ull acc[4][4];                       // [q][dp]
        #pragma unroll
        for (int q = 0; q < 4; ++q)
            #pragma unroll
            for (int dp = 0; dp < 4; ++dp) acc[q][dp] = 0ULL;
        #pragma unroll 2
        for (int s = 0; s < FN; ++s) {
            const ull* ar = (const ull*)(A1 + (h * FN + s) * A1PAD + dg * 8);
            ull a0 = ar[0], a1 = ar[1], a2 = ar[2], a3 = ar[3];
            const float* xr = X + s * XPAD + lane;
            ull x0 = splat2(xr[0]);
            ull x1 = splat2(xr[32]);
            ull x2 = splat2(xr[64]);
            ull x3 = splat2(xr[96]);
            fma2(acc[0][0], a0, x0); fma2(acc[0][1], a1, x0);
            fma2(acc[0][2], a2, x0); fma2(acc[0][3], a3, x0);
            fma2(acc[1][0], a0, x1); fma2(acc[1][1], a1, x1);
            fma2(acc[1][2], a2, x1); fma2(acc[1][3], a3, x1);
            fma2(acc[2][0], a0, x2); fma2(acc[2][1], a1, x2);
            fma2(acc[2][2], a2, x2); fma2(acc[2][3], a3, x2);
            fma2(acc[3][0], a0, x3); fma2(acc[3][1], a1, x3);
            fma2(acc[3][2], a2, x3); fma2(acc[3][3], a3, x3);
        }
        ull iv[4];
        #pragma unroll
        for (int dp = 0; dp < 4; ++dp) {
            float i0 = __shfl_sync(0xffffffffu, myinv, 2 * dp);
            float i1 = __shfl_sync(0xffffffffu, myinv, 2 * dp + 1);
            iv[dp] = pk2(i0, i1);
        }
        #pragma unroll
        for (int q = 0; q < 4; ++q) {
            int k = lane + 32 * q;
            float* yb = yT + (h * HID + k) * YTPAD + dg * 8;
            #pragma unroll
            for (int dp = 0; dp < 4; ++dp) {
                mul2(acc[q][dp], iv[dp]);
                *(ull*)(yb + 2 * dp) = acc[q][dp];
            }
        }
    }
    __syncthreads();

    // ---------- Phase 5: h1 = ELU(y @ W1 + b1) (32 warps, 8r x 64c) --------
    // warp = (rg, h, ch); lane covers 2 consecutive columns c, c+1
    {
        const int rg = wid >> 3;            // rows rg*8..+7 (4 pairs)
        const int h  = (wid >> 1) & 3;
        const int ch = wid & 1;
        const int c  = h * HID + ch * 64 + lane * 2;
        ull acc[4][2];
        #pragma unroll
        for (int p = 0; p < 4; ++p) { acc[p][0] = 0ULL; acc[p][1] = 0ULL; }
        const float* yh = yT + h * HID * YTPAD + rg * 8;
        #pragma unroll 4
        for (int k = 0; k < HID; ++k) {
            float2 w = *(const float2*)(W1 + k * H4 + c);
            ull wb0 = splat2(w.x), wb1 = splat2(w.y);
            const ulonglong2* yp = (const ulonglong2*)(yh + k * YTPAD);
            ulonglong2 y01 = yp[0];
            ulonglong2 y23 = yp[1];
            fma2(acc[0][0], y01.x, wb0); fma2(acc[0][1], y01.x, wb1);
            fma2(acc[1][0], y01.y, wb0); fma2(acc[1][1], y01.y, wb1);
            fma2(acc[2][0], y23.x, wb0); fma2(acc[2][1], y23.x, wb1);
            fma2(acc[3][0], y23.y, wb0); fma2(acc[3][1], y23.y, wb1);
        }
        float2 bb  = *(const float2*)(b1 + c);
        float2 w2s = *(const float2*)(g_wt2s + c);
        float2 w2d = *(const float2*)(g_wt2d + c);
        #pragma unroll
        for (int p = 0; p < 4; ++p) {
            int d0 = rg * 8 + p * 2;
            float v00, v10, v01, v11;
            upk2(acc[p][0], v00, v10);     // col c : rows d0, d0+1
            upk2(acc[p][1], v01, v11);     // col c+1
            v00 = elu1(v00 + bb.x); v01 = elu1(v01 + bb.y);
            v10 = elu1(v10 + bb.x); v11 = elu1(v11 + bb.y);
            *(float2*)(H1 + d0 * H1PAD + c)       = make_float2(v00, v01);
            *(float2*)(H1 + (d0 + 1) * H1PAD + c) = make_float2(v10, v11);
            float s0  = wredsum(fmaf(v00, w2s.x, v01 * w2s.y));
            float d0s = wredsum(fmaf(v00, w2d.x, v01 * w2d.y));
            float s1  = wredsum(fmaf(v10, w2s.x, v11 * w2s.y));
            float d1s = wredsum(fmaf(v10, w2d.x, v11 * w2d.y));
            if (lane == 0) {
                atomicAdd(&as2[d0], s0);
                atomicAdd(&ad2[d0], d0s);
                atomicAdd(&as2[d0 + 1], s1);
                atomicAdd(&ad2[d0 + 1], d1s);
            }
        }
    }
    __syncthreads();

    // ---------- Phase 6: edge pass 2 (lbuf) -> csr -------------------------
    if (tid < ETOT) {
        int s = sSL[tid], d = sDL[tid];
        float l = as2[s] + ad2[d];
        l = (l > 0.f) ? l : 0.2f * l;
        float ex = __expf(l);
        lbuf[tid] = ex;
        atomicAdd(&dn2[d], ex);
    }
    __syncthreads();
    if (tid < 32) iv2[tid] = __fdividef(1.f, dn2[tid] * (float)FN);
    __syncthreads();
    if (tid < ETOT) {
        atomicAdd(&csr[sSL[tid]], lbuf[tid] * iv2[sDL[tid]]);
    }
    __syncthreads();

    // ---------- Phase 7: zbar[k] = sum_s csr[s] * H1[s,k] ------------------
    if (tid < 512) {
        float acc = 0.f;
        #pragma unroll 8
        for (int s = 0; s < FN; ++s) acc = fmaf(csr[s], H1[s * H1PAD + tid], acc);
        zb[tid] = acc;
    }
    __syncthreads();

    // ---------- Phase 8: out = zbar @ W2 + b2 (8-way k-split) --------------
    {
        const int cc = tid & 127;
        const int ks = tid >> 7;             // 8 k-splits of 64
        const float* w2 = W2 + (ks * 64) * HID + cc;
        const float* zp = zb + ks * 64;
        float a0 = 0.f, a1 = 0.f, a2 = 0.f, a3 = 0.f;
        #pragma unroll 4
        for (int k = 0; k < 64; k += 4) {
            a0 = fmaf(zp[k + 0], w2[(k + 0) * HID], a0);
            a1 = fmaf(zp[k + 1], w2[(k + 1) * HID], a1);
            a2 = fmaf(zp[k + 2], w2[(k + 2) * HID], a2);
            a3 = fmaf(zp[k + 3], w2[(k + 3) * HID], a3);
        }
        ps[tid] = (a0 + a1) + (a2 + a3);
    }
    __syncthreads();
    if (tid < HID) {
        float tot = 0.f;
        #pragma unroll
        for (int q = 0; q < 8; ++q) tot += ps[q * 128 + tid];
        out[(size_t)g * HID + tid] = tot + b2[tid];
    }
    if (write_gate && g == 0 && tid < FN) {
        out[(size_t)BGRAPH * HID + tid] = 1.f / (1.f + __expf(-gatel[tid]));
    }
}

extern "C" void kernel_launch(void* const* d_in, const int* in_sizes, int n_in,
                              void* d_out, int out_size)
{
    const float* emb   = (const float*)d_in[0];
    const float* Wal   = (const float*)d_in[1];
    const float* bal   = (const float*)d_in[2];
    const float* lng   = (const float*)d_in[3];
    const float* lnb   = (const float*)d_in[4];
    const float* gatel = (const float*)d_in[5];
    const float* W1    = (const float*)d_in[6];
    const float* as1w  = (const float*)d_in[7];
    const float* ad1w  = (const float*)d_in[8];
    const float* b1    = (const float*)d_in[9];
    const float* W2    = (const float*)d_in[10];
    const float* as2w  = (const float*)d_in[11];
    const float* ad2w  = (const float*)d_in[12];
    const float* b2    = (const float*)d_in[13];
    const int*   ei    = (const int*)d_in[14];

    const int Et = in_sizes[14] / 2;
    const int* esrc = ei;
    const int* edst = ei + Et;
    const int write_gate = (out_size >= BGRAPH * HID + FN) ? 1 : 0;

    cudaFuncSetAttribute(gat_fused_kernel,
                         cudaFuncAttributeMaxDynamicSharedMemorySize, SMEM_BYTES);

    precomp_kernel<<<2, 512>>>(W1, as1w, ad1w, W2, as2w, ad2w);
    gat_fused_kernel<<<BGRAPH, NTH, SMEM_BYTES>>>(
        emb, Wal, bal, lng, lnb, gatel,
        W1, b1, W2, b2,
        esrc, edst, (float*)d_out, write_gate);
}

// round 11
// speedup vs baseline: 1.4153x; 1.1431x over previous
#include <cuda_runtime.h>

// ---------------- problem constants ----------------------------------------
#define BGRAPH 1024
#define FN     32
#define DIN    64
#define HID    128
#define NHEADS 4
#define EPG    256
#define ETOT   (EPG + FN)       // 288
#define H4     (NHEADS * HID)   // 512
#define XPAD   128
#define YTPAD  34
#define ETPAD  34
#define A1PAD  34
#define NTH    512

// ---------------- shared memory layout (float offsets) ---------------------
#define SM_YT   0                      // yT [4][128][34] = 17408 (embT overlays)
#define SM_X    17408                  // X [32][128] = 4096
#define SM_A1   21504                  // [4][32][34] = 4352
#define SM_LB   25856                  // 288
#define SM_AS1  26144                  // 128
#define SM_AD1  26272                  // 128
#define SM_AS2  26400                  // 32
#define SM_AD2  26432                  // 32
#define SM_DN2  26464                  // 32
#define SM_IV2  26496                  // 32
#define SM_CSR  26528                  // 32
#define SM_ZB   26560                  // 512
#define SM_PS   27072                  // 512
#define SM_NF   27584
#define SM_NI   (2 * ETOT)             // 576 ints
#define SMEM_BYTES ((SM_NF + SM_NI) * 4)   // 112,640 B -> 2 CTAs/SM

typedef unsigned long long ull;

__device__ float g_wts1[512];   // [h][k] = sum_c W1[k, h*128+c] * att_src1[h,c]
__device__ float g_wtd1[512];
__device__ float g_wt2s[512];   // [k]    = sum_c W2[k,c] * att_src2[c]
__device__ float g_wt2d[512];

__device__ __forceinline__ ull pk2(float x, float y) {
    ull r; asm("mov.b64 %0, {%1,%2};" : "=l"(r) : "f"(x), "f"(y)); return r;
}
__device__ __forceinline__ ull splat2(float x) { return pk2(x, x); }
__device__ __forceinline__ void upk2(ull p, float& x, float& y) {
    asm("mov.b64 {%0,%1}, %2;" : "=f"(x), "=f"(y) : "l"(p));
}
__device__ __forceinline__ void fma2(ull& d, ull a, ull b) {
    asm("fma.rn.f32x2 %0, %1, %2, %0;" : "+l"(d) : "l"(a), "l"(b));
}
__device__ __forceinline__ void mul2(ull& d, ull b) {
    asm("mul.rn.f32x2 %0, %0, %1;" : "+l"(d) : "l"(b));
}
__device__ __forceinline__ float dot4(const float4& a, const float4& b) {
    return fmaf(a.x, b.x, fmaf(a.y, b.y, fmaf(a.z, b.z, a.w * b.w)));
}
__device__ __forceinline__ float wredsum(float v) {
    #pragma unroll
    for (int o = 16; o; o >>= 1) v += __shfl_xor_sync(0xffffffffu, v, o);
    return v;
}
__device__ __forceinline__ float elu1(float x) {
    return (x > 0.f) ? x : expm1f(x);
}

// ---------------- pre-kernel: project attention vectors through weights ----
__global__ void precomp_kernel(const float* __restrict__ W1,
                               const float* __restrict__ as1w,
                               const float* __restrict__ ad1w,
                               const float* __restrict__ W2,
                               const float* __restrict__ as2w,
                               const float* __restrict__ ad2w)
{
    int t = blockIdx.x * blockDim.x + threadIdx.x;   // 0..1023
    if (t < 512) {
        int h = t >> 7, k = t & 127;
        const float* wrow = W1 + k * H4 + h * HID;
        const float* aw = as1w + h * HID;
        const float* dw = ad1w + h * HID;
        float s = 0.f, d = 0.f;
        #pragma unroll 4
        for (int c = 0; c < HID; ++c) {
            s = fmaf(wrow[c], aw[c], s);
            d = fmaf(wrow[c], dw[c], d);
        }
        g_wts1[t] = s; g_wtd1[t] = d;
    } else {
        int k = t - 512;
        const float* wrow = W2 + k * HID;
        float s = 0.f, d = 0.f;
        #pragma unroll 4
        for (int c = 0; c < HID; ++c) {
            s = fmaf(wrow[c], as2w[c], s);
            d = fmaf(wrow[c], ad2w[c], d);
        }
        g_wt2s[k] = s; g_wt2d[k] = d;
    }
}

__global__ __launch_bounds__(NTH, 2)
void gat_fused_kernel(
    const float* __restrict__ emb,    const float* __restrict__ Wal,
    const float* __restrict__ bal,    const float* __restrict__ lng,
    const float* __restrict__ lnb,    const float* __restrict__ gatel,
    const float* __restrict__ W1,     const float* __restrict__ b1,
    const float* __restrict__ W2,     const float* __restrict__ b2,
    const int*   __restrict__ esrc,   const int*   __restrict__ edst,
    float*       __restrict__ out,    int write_gate)
{
    extern __shared__ float sm[];
    float* yT   = sm + SM_YT;             // [4][128][34]
    float* embT = sm + SM_YT;             // [64][34] overlay (dead before yT)
    float* X    = sm + SM_X;              // [32][128]
    float* A1   = sm + SM_A1;
    float* lbuf = sm + SM_LB;
    float* as1  = sm + SM_AS1;
    float* ad1  = sm + SM_AD1;
    float* as2  = sm + SM_AS2;
    float* ad2  = sm + SM_AD2;
    float* dn2  = sm + SM_DN2;
    float* iv2  = sm + SM_IV2;
    float* csr  = sm + SM_CSR;
    float* zb   = sm + SM_ZB;
    float* ps   = sm + SM_PS;
    int* sSL = (int*)(sm + SM_NF);
    int* sDL = sSL + ETOT;

    const int g    = blockIdx.x;
    const int tid  = threadIdx.x;
    const int lane = tid & 31;
    const int wid  = tid >> 5;

    // ---------- Phase 0: stage embT + edges, zero accumulators -------------
    {
        float4 v = ((const float4*)emb)[(size_t)g * (FN * DIN / 4) + tid];
        int r  = tid >> 4;
        int c4 = tid & 15;
        embT[(c4 * 4 + 0) * ETPAD + r] = v.x;
        embT[(c4 * 4 + 1) * ETPAD + r] = v.y;
        embT[(c4 * 4 + 2) * ETPAD + r] = v.z;
        embT[(c4 * 4 + 3) * ETPAD + r] = v.w;
    }
    if (tid < 256) {
        sSL[tid] = esrc[g * EPG + tid] - g * FN;
        sDL[tid] = edst[g * EPG + tid] - g * FN;
    }
    if (tid < 32) {
        sSL[EPG + tid] = tid;  sDL[EPG + tid] = tid;   // self loops
        as2[tid] = 0.f; ad2[tid] = 0.f; dn2[tid] = 0.f; csr[tid] = 0.f;
    }
    for (int i = tid; i < (4 * FN * A1PAD) / 4; i += NTH)
        ((float4*)A1)[i] = make_float4(0.f, 0.f, 0.f, 0.f);
    zb[tid] = 0.f;
    __syncthreads();

    // ---------- Phase 1: align GEMM + in-register LN/gate/logits1 ----------
    {
        ull acc[4];
        #pragma unroll
        for (int j = 0; j < 4; ++j) acc[j] = 0ULL;
        const float4* Wp = (const float4*)Wal + lane;
        #pragma unroll 4
        for (int k = 0; k < DIN; ++k) {
            float4 b = Wp[k * 32];
            ull a0 = *(const ull*)(embT + k * ETPAD + wid * 2);
            fma2(acc[0], a0, splat2(b.x));
            fma2(acc[1], a0, splat2(b.y));
            fma2(acc[2], a0, splat2(b.z));
            fma2(acc[3], a0, splat2(b.w));
        }
        float4 bb = ((const float4*)bal)[lane];
        float4 r0, r1;
        upk2(acc[0], r0.x, r1.x); upk2(acc[1], r0.y, r1.y);
        upk2(acc[2], r0.z, r1.z); upk2(acc[3], r0.w, r1.w);
        r0.x += bb.x; r0.y += bb.y; r0.z += bb.z; r0.w += bb.w;
        r1.x += bb.x; r1.y += bb.y; r1.z += bb.z; r1.w += bb.w;
        float4 lg = ((const float4*)lng)[lane];
        float4 lb = ((const float4*)lnb)[lane];
        const int row0 = wid * 2;
        float s0 = wredsum(r0.x + r0.y + r0.z + r0.w);
        float q0 = wredsum(dot4(r0, r0));
        float s1 = wredsum(r1.x + r1.y + r1.z + r1.w);
        float q1 = wredsum(dot4(r1, r1));
        float m0 = s0 * (1.f / HID);
        float m1 = s1 * (1.f / HID);
        float rs0 = rsqrtf(q0 * (1.f / HID) - m0 * m0 + 1e-5f);
        float rs1 = rsqrtf(q1 * (1.f / HID) - m1 * m1 + 1e-5f);
        float g0 = 1.f / (1.f + __expf(-gatel[row0]));
        float g1 = 1.f / (1.f + __expf(-gatel[row0 + 1]));
        float4 x0, x1;
        x0.x = ((r0.x - m0) * rs0 * lg.x + lb.x) * g0;
        x0.y = ((r0.y - m0) * rs0 * lg.y + lb.y) * g0;
        x0.z = ((r0.z - m0) * rs0 * lg.z + lb.z) * g0;
        x0.w = ((r0.w - m0) * rs0 * lg.w + lb.w) * g0;
        x1.x = ((r1.x - m1) * rs1 * lg.x + lb.x) * g1;
        x1.y = ((r1.y - m1) * rs1 * lg.y + lb.y) * g1;
        x1.z = ((r1.z - m1) * rs1 * lg.z + lb.z) * g1;
        x1.w = ((r1.w - m1) * rs1 * lg.w + lb.w) * g1;
        ((float4*)(X + row0 * XPAD))[lane]       = x0;
        ((float4*)(X + (row0 + 1) * XPAD))[lane] = x1;
        #pragma unroll
        for (int h = 0; h < NHEADS; ++h) {
            float4 ws = ((const float4*)g_wts1)[h * 32 + lane];
            float4 wd = ((const float4*)g_wtd1)[h * 32 + lane];
            float a0s = wredsum(dot4(x0, ws));
            float a0d = wredsum(dot4(x0, wd));
            float a1s = wredsum(dot4(x1, ws));
            float a1d = wredsum(dot4(x1, wd));
            if (lane == 0) {
                as1[row0 * 4 + h] = a0s;       ad1[row0 * 4 + h] = a0d;
                as1[(row0 + 1) * 4 + h] = a1s; ad1[(row0 + 1) * 4 + h] = a1d;
            }
        }
    }
    __syncthreads();

    // ---------- Phase 3: edge pass 1 -> dense A1 ---------------------------
    {
        int h = tid & 3;
        for (int e = tid >> 2; e < ETOT; e += 128) {
            int s = sSL[e], d = sDL[e];
            float l = as1[s * 4 + h] + ad1[d * 4 + h];
            l = (l > 0.f) ? l : 0.2f * l;
            atomicAdd(&A1[(h * FN + s) * A1PAD + d], __expf(l));
        }
    }
    __syncthreads();

    // ---------- Phase 4: y = A1n^T @ x (16 warps, inline inv1) -> yT -------
    {
        const int h  = wid >> 2;
        const int dg = wid & 3;
        int myd = dg * 8 + (lane & 7);
        float csum = 0.f;
        #pragma unroll 8
        for (int s = 0; s < FN; ++s) csum += A1[(h * FN + s) * A1PAD + myd];
        float myinv = __fdividef(1.f, csum);
        ull acc[4][4];                       // [q][dp]
        #pragma unroll
        for (int q = 0; q < 4; ++q)
            #pragma unroll
            for (int dp = 0; dp < 4; ++dp) acc[q][dp] = 0ULL;
        #pragma unroll 2
        for (int s = 0; s < FN; ++s) {
            const ull* ar = (const ull*)(A1 + (h * FN + s) * A1PAD + dg * 8);
            ull a0 = ar[0], a1 = ar[1], a2 = ar[2], a3 = ar[3];
            const float* xr = X + s * XPAD + lane;
            ull x0 = splat2(xr[0]);
            ull x1 = splat2(xr[32]);
            ull x2 = splat2(xr[64]);
            ull x3 = splat2(xr[96]);
            fma2(acc[0][0], a0, x0); fma2(acc[0][1], a1, x0);
            fma2(acc[0][2], a2, x0); fma2(acc[0][3], a3, x0);
            fma2(acc[1][0], a0, x1); fma2(acc[1][1], a1, x1);
            fma2(acc[1][2], a2, x1); fma2(acc[1][3], a3, x1);
            fma2(acc[2][0], a0, x2); fma2(acc[2][1], a1, x2);
            fma2(acc[2][2], a2, x2); fma2(acc[2][3], a3, x2);
            fma2(acc[3][0], a0, x3); fma2(acc[3][1], a1, x3);
            fma2(acc[3][2], a2, x3); fma2(acc[3][3], a3, x3);
        }
        ull iv[4];
        #pragma unroll
        for (int dp = 0; dp < 4; ++dp) {
            float i0 = __shfl_sync(0xffffffffu, myinv, 2 * dp);
            float i1 = __shfl_sync(0xffffffffu, myinv, 2 * dp + 1);
            iv[dp] = pk2(i0, i1);
        }
        #pragma unroll
        for (int q = 0; q < 4; ++q) {
            int k = lane + 32 * q;
            float* yb = yT + (h * HID + k) * YTPAD + dg * 8;
            #pragma unroll
            for (int dp = 0; dp < 4; ++dp) {
                mul2(acc[q][dp], iv[dp]);
                *(ull*)(yb + 2 * dp) = acc[q][dp];
            }
        }
    }
    __syncthreads();

    // ---------- Phase 5: h1 = ELU(y @ W1 + b1) in REGISTERS ----------------
    // 16 warps: warp = (rg, h), 8 rows x 128 cols; acc[p][j] holds rows
    // (rg*8+2p, +1) for column h*128 + lane*4 + j. h1 never touches smem.
    ull acc[4][4];
    {
        const int rg = wid >> 2;
        const int h  = wid & 3;
        #pragma unroll
        for (int p = 0; p < 4; ++p)
            #pragma unroll
            for (int j = 0; j < 4; ++j) acc[p][j] = 0ULL;
        const float4* Wp = (const float4*)W1 + h * 32 + lane;
        const float* yh = yT + h * HID * YTPAD + rg * 8;
        #pragma unroll 2
        for (int k = 0; k < HID; ++k) {
            float4 w = Wp[k * 128];
            ull b0 = splat2(w.x), b1v = splat2(w.y);
            ull b2v = splat2(w.z), b3 = splat2(w.w);
            const ull* ap = (const ull*)(yh + k * YTPAD);
            ull a0 = ap[0], a1 = ap[1], a2 = ap[2], a3 = ap[3];
            fma2(acc[0][0], a0, b0); fma2(acc[0][1], a0, b1v);
            fma2(acc[0][2], a0, b2v); fma2(acc[0][3], a0, b3);
            fma2(acc[1][0], a1, b0); fma2(acc[1][1], a1, b1v);
            fma2(acc[1][2], a1, b2v); fma2(acc[1][3], a1, b3);
            fma2(acc[2][0], a2, b0); fma2(acc[2][1], a2, b1v);
            fma2(acc[2][2], a2, b2v); fma2(acc[2][3], a2, b3);
            fma2(acc[3][0], a3, b0); fma2(acc[3][1], a3, b1v);
            fma2(acc[3][2], a3, b2v); fma2(acc[3][3], a3, b3);
        }
        // epilogue: bias + ELU (repack into acc), logits2 partials
        float4 bb  = ((const float4*)b1)[h * 32 + lane];
        float4 w2s = ((const float4*)g_wt2s)[h * 32 + lane];
        float4 w2d = ((const float4*)g_wt2d)[h * 32 + lane];
        #pragma unroll
        for (int p = 0; p < 4; ++p) {
            int d0 = rg * 8 + p * 2;
            float4 r0, r1;
            upk2(acc[p][0], r0.x, r1.x); upk2(acc[p][1], r0.y, r1.y);
            upk2(acc[p][2], r0.z, r1.z); upk2(acc[p][3], r0.w, r1.w);
            r0.x = elu1(r0.x + bb.x); r0.y = elu1(r0.y + bb.y);
            r0.z = elu1(r0.z + bb.z); r0.w = elu1(r0.w + bb.w);
            r1.x = elu1(r1.x + bb.x); r1.y = elu1(r1.y + bb.y);
            r1.z = elu1(r1.z + bb.z); r1.w = elu1(r1.w + bb.w);
            acc[p][0] = pk2(r0.x, r1.x);
            acc[p][1] = pk2(r0.y, r1.y);
            acc[p][2] = pk2(r0.z, r1.z);
            acc[p][3] = pk2(r0.w, r1.w);
            float s0  = wredsum(dot4(r0, w2s));
            float d0s = wredsum(dot4(r0, w2d));
            float s1  = wredsum(dot4(r1, w2s));
            float d1s = wredsum(dot4(r1, w2d));
            if (lane == 0) {
                atomicAdd(&as2[d0], s0);
                atomicAdd(&ad2[d0], d0s);
                atomicAdd(&as2[d0 + 1], s1);
                atomicAdd(&ad2[d0 + 1], d1s);
            }
        }
    }
    __syncthreads();

    // ---------- Phase 6: edge pass 2 (lbuf) -> csr -------------------------
    if (tid < ETOT) {
        int s = sSL[tid], d = sDL[tid];
        float l = as2[s] + ad2[d];
        l = (l > 0.f) ? l : 0.2f * l;
        float ex = __expf(l);
        lbuf[tid] = ex;
        atomicAdd(&dn2[d], ex);
    }
    __syncthreads();
    if (tid < 32) iv2[tid] = __fdividef(1.f, dn2[tid] * (float)FN);
    __syncthreads();
    if (tid < ETOT) {
        atomicAdd(&csr[sSL[tid]], lbuf[tid] * iv2[sDL[tid]]);
    }
    __syncthreads();

    // ---------- Phase 7': zbar from register-resident h1 -------------------
    {
        const int rg = wid >> 2;
        const int h  = wid & 3;
        ull csrp[4];
        #pragma unroll
        for (int p = 0; p < 4; ++p)
            csrp[p] = pk2(csr[rg * 8 + 2 * p], csr[rg * 8 + 2 * p + 1]);
        #pragma unroll
        for (int j = 0; j < 4; ++j) {
            ull za = 0ULL;
            #pragma unroll
            for (int p = 0; p < 4; ++p) fma2(za, csrp[p], acc[p][j]);
            float lo, hi;
            upk2(za, lo, hi);
            atomicAdd(&zb[h * HID + lane * 4 + j], lo + hi);
        }
    }
    __syncthreads();

    // ---------- Phase 8: out = zbar @ W2 + b2 (4-way k-split) --------------
    {
        const int cc = tid & 127;
        const int ks = tid >> 7;             // 4 k-splits of 128
        const float* w2 = W2 + (ks * 128) * HID + cc;
        const float* zp = zb + ks * 128;
        float a0 = 0.f, a1 = 0.f, a2 = 0.f, a3 = 0.f;
        #pragma unroll 8
        for (int k = 0; k < 128; k += 4) {
            a0 = fmaf(zp[k + 0], w2[(k + 0) * HID], a0);
            a1 = fmaf(zp[k + 1], w2[(k + 1) * HID], a1);
            a2 = fmaf(zp[k + 2], w2[(k + 2) * HID], a2);
            a3 = fmaf(zp[k + 3], w2[(k + 3) * HID], a3);
        }
        ps[tid] = (a0 + a1) + (a2 + a3);
    }
    __syncthreads();
    if (tid < HID) {
        float tot = ps[tid] + ps[128 + tid] + ps[256 + tid] + ps[384 + tid];
        out[(size_t)g * HID + tid] = tot + b2[tid];
    }
    if (write_gate && g == 0 && tid < FN) {
        out[(size_t)BGRAPH * HID + tid] = 1.f / (1.f + __expf(-gatel[tid]));
    }
}

extern "C" void kernel_launch(void* const* d_in, const int* in_sizes, int n_in,
                              void* d_out, int out_size)
{
    const float* emb   = (const float*)d_in[0];
    const float* Wal   = (const float*)d_in[1];
    const float* bal   = (const float*)d_in[2];
    const float* lng   = (const float*)d_in[3];
    const float* lnb   = (const float*)d_in[4];
    const float* gatel = (const float*)d_in[5];
    const float* W1    = (const float*)d_in[6];
    const float* as1w  = (const float*)d_in[7];
    const float* ad1w  = (const float*)d_in[8];
    const float* b1    = (const float*)d_in[9];
    const float* W2    = (const float*)d_in[10];
    const float* as2w  = (const float*)d_in[11];
    const float* ad2w  = (const float*)d_in[12];
    const float* b2    = (const float*)d_in[13];
    const int*   ei    = (const int*)d_in[14];

    const int Et = in_sizes[14] / 2;
    const int* esrc = ei;
    const int* edst = ei + Et;
    const int write_gate = (out_size >= BGRAPH * HID + FN) ? 1 : 0;

    cudaFuncSetAttribute(gat_fused_kernel,
                         cudaFuncAttributeMaxDynamicSharedMemorySize, SMEM_BYTES);

    precomp_kernel<<<2, 512>>>(W1, as1w, ad1w, W2, as2w, ad2w);
    gat_fused_kernel<<<BGRAPH, NTH, SMEM_BYTES>>>(
        emb, Wal, bal, lng, lnb, gatel,
        W1, b1, W2, b2,
        esrc, edst, (float*)d_out, write_gate);
}